// round 11
// baseline (speedup 1.0000x reference)
#include <cuda_runtime.h>
#include <stdint.h>

// Problem constants (fixed by the reference: B=64, T=2048, D=64, V=100000)
#define BB 64
#define TT 2048
#define DD 64
#define NROWS (4 * BB)          // 4 features x 64 batches
#define BT (BB * TT)            // 131072

// Output layout (floats), tuple flattened in order:
//   features [B,T,256] @ 0
//   times    [B,T]     @ BT*256
//   delta    [B,T,256] @ BT*256 + BT
//   mask     [B,T,256] @ BT*256 + BT + BT*256
#define OFF_TIMES  (BT * 256)                 // 33554432
#define OFF_DELTA  (OFF_TIMES + BT)           // 33685504
#define OFF_MASK   (OFF_DELTA + BT * 256)     // 67239936

// Beta scratch, TRANSPOSED: g_beta[gw*4 + f] so emit reads one float4/warp.
__device__ float g_beta[4 * BT];

// ---------------------------------------------------------------------------
// Kernel 1: beta linear-recurrence scan.
// x_t = a_t * x_{t-1} + c_t, a_t = m_{t-1}*p_t, c_t = dt_t*p_t, x_0 = 0.
// One 256-thread block per (f,b) row, 8 elems/thread, vectorized loads.
// ---------------------------------------------------------------------------
__global__ __launch_bounds__(256) void beta_scan_kernel(
    const int*   __restrict__ cat1,
    const int*   __restrict__ cat2,
    const float* __restrict__ num1,
    const float* __restrict__ num2,
    const float* __restrict__ times)
{
    const int row  = blockIdx.x;        // 0..255
    const int f    = row >> 6;          // 0..3
    const int b    = row & 63;          // 0..63
    const int tid  = threadIdx.x;       // 0..255
    const int lane = tid & 31;
    const int wid  = tid >> 5;          // 0..7

    __shared__ float sA[8], sC[8];

    const float* tr = times + b * TT;
    const int t0 = tid * 8;

    // ---- vectorized time loads: tv[0..7] = tr[t0..t0+7] ----
    const float4 ta = __ldg(reinterpret_cast<const float4*>(tr + t0));
    const float4 tb = __ldg(reinterpret_cast<const float4*>(tr + t0 + 4));
    float tv[8] = {ta.x, ta.y, ta.z, ta.w, tb.x, tb.y, tb.z, tb.w};

    // tr[t0-1]: previous lane's tv[7]; lane 0 loads scalar
    float tprev = __shfl_up_sync(0xffffffffu, tv[7], 1);
    if (lane == 0) tprev = (t0 > 0) ? __ldg(tr + t0 - 1) : 0.0f;

    // ---- feature mask values m[k] for feat[t0+k-1], k=0..7 ----
    float m[8];
    if (f < 2) {
        const int* cr = (f == 0 ? cat1 : cat2) + b * TT;
        const int4 va = __ldg(reinterpret_cast<const int4*>(cr + t0));
        const int4 vb = __ldg(reinterpret_cast<const int4*>(cr + t0 + 4));
        int fv[8] = {va.x, va.y, va.z, va.w, vb.x, vb.y, vb.z, vb.w};
        int fprev = __shfl_up_sync(0xffffffffu, fv[7], 1);
        if (lane == 0) fprev = (t0 > 0) ? __ldg(cr + t0 - 1) : 0;
        m[0] = (fprev != 0 && fprev != -1) ? 1.0f : 0.0f;
        #pragma unroll
        for (int k = 1; k < 8; ++k)
            m[k] = (fv[k - 1] != 0 && fv[k - 1] != -1) ? 1.0f : 0.0f;
    } else {
        const float* nr = (f == 2 ? num1 : num2) + b * TT;
        const float4 va = __ldg(reinterpret_cast<const float4*>(nr + t0));
        const float4 vb = __ldg(reinterpret_cast<const float4*>(nr + t0 + 4));
        float fv[8] = {va.x, va.y, va.z, va.w, vb.x, vb.y, vb.z, vb.w};
        float fprev = __shfl_up_sync(0xffffffffu, fv[7], 1);
        if (lane == 0) fprev = (t0 > 0) ? __ldg(nr + t0 - 1) : 0.0f;
        m[0] = (fprev != 0.0f && fprev != -1.0f) ? 1.0f : 0.0f;
        #pragma unroll
        for (int k = 1; k < 8; ++k)
            m[k] = (fv[k - 1] != 0.0f && fv[k - 1] != -1.0f) ? 1.0f : 0.0f;
    }

    // ---- per-element coefficients ----
    float a[8], c[8];
    #pragma unroll
    for (int k = 0; k < 8; ++k) {
        const float tkm1 = (k == 0) ? tprev : tv[k - 1];
        const float p  = (tv[k] != -1.0f) ? 1.0f : 0.0f;
        a[k] = m[k] * p;
        c[k] = (tv[k] - tkm1) * p;
    }
    if (t0 == 0) { a[0] = 0.0f; c[0] = 0.0f; }   // beta[0] = 0

    // ---- sequential composition of this thread's 8 elements ----
    float A = a[0], C = c[0];
    #pragma unroll
    for (int k = 1; k < 8; ++k) { C = c[k] + a[k] * C; A = a[k] * A; }

    // ---- warp inclusive scan of thread-compositions ----
    #pragma unroll
    for (int off = 1; off < 32; off <<= 1) {
        const float Ap = __shfl_up_sync(0xffffffffu, A, off);
        const float Cp = __shfl_up_sync(0xffffffffu, C, off);
        if (lane >= off) { C = C + A * Cp; A = A * Ap; }
    }
    if (lane == 31) { sA[wid] = A; sC[wid] = C; }
    __syncthreads();

    // ---- tiny serial exclusive scan over 8 warp aggregates ----
    if (tid == 0) {
        float Ae = 1.0f, Ce = 0.0f;
        #pragma unroll
        for (int i = 0; i < 8; ++i) {
            const float Ai = sA[i], Ci = sC[i];
            sA[i] = Ae; sC[i] = Ce;
            Ce = Ci + Ai * Ce;
            Ae = Ai * Ae;
        }
    }
    __syncthreads();

    // ---- thread-exclusive prefix (x starts at 0 -> only C terms survive) ----
    float Ax = __shfl_up_sync(0xffffffffu, A, 1);
    float Cx = __shfl_up_sync(0xffffffffu, C, 1);
    if (lane == 0) { Ax = 1.0f; Cx = 0.0f; }
    float x = Cx + Ax * sC[wid];

    // ---- apply elementwise, store TRANSPOSED: g_beta[(b*TT+t)*4 + f] ----
    const int gw0 = b * TT + t0;
    #pragma unroll
    for (int k = 0; k < 8; ++k) {
        x = c[k] + a[k] * x;
        g_beta[(size_t)(gw0 + k) * 4 + f] = x;
    }
}

// ---------------------------------------------------------------------------
// Kernel 2: emit all outputs (R6 config — best measured). One warp per (b,t),
// branchless lane-selects, loads batched ahead of the store burst, __stcs on
// all output stores. Beta now read as ONE float4 per warp (transposed layout).
// ---------------------------------------------------------------------------
__global__ void emit_kernel(const int*   __restrict__ cat1,
                            const int*   __restrict__ cat2,
                            const float* __restrict__ num1,
                            const float* __restrict__ num2,
                            const float* __restrict__ times,
                            const float* __restrict__ E1,
                            const float* __restrict__ E2,
                            const float* __restrict__ w1,
                            const float* __restrict__ b1,
                            const float* __restrict__ w2,
                            const float* __restrict__ b2,
                            float* __restrict__ out)
{
    const int gw   = blockIdx.x * (blockDim.x >> 5) + (threadIdx.x >> 5); // (b,t)
    const int lane = threadIdx.x & 31;

    const bool lo = (lane < 16);
    const int  sl = lo ? lane : (lane - 16);   // sub-lane within 16

    // --- batch all scalar loads (independent, high MLP) ---
    const int   c1 = __ldg(cat1 + gw);
    const int   c2 = __ldg(cat2 + gw);
    const float n1 = __ldg(num1 + gw);
    const float n2 = __ldg(num2 + gw);
    const float tm = __ldg(times + gw);

    // one coalesced float4: (be0, be1, be2, be3) for this (b,t)
    const float4 be = *reinterpret_cast<const float4*>(g_beta + (size_t)gw * 4);

    // --- half 0 gather: lanes 0-15 -> E1 row, lanes 16-31 -> E2 row ---
    const float4* e1row = reinterpret_cast<const float4*>(E1 + (size_t)c1 * DD);
    const float4* e2row = reinterpret_cast<const float4*>(E2 + (size_t)c2 * DD);
    const float4* src0  = lo ? (e1row + sl) : (e2row + sl);
    const float4  v0    = __ldg(src0);

    // --- half 1: lanes 0-15 -> n1*w1+b1, lanes 16-31 -> n2*w2+b2 ---
    const float4* wsrc = lo ? (reinterpret_cast<const float4*>(w1) + sl)
                            : (reinterpret_cast<const float4*>(w2) + sl);
    const float4* osrc = lo ? (reinterpret_cast<const float4*>(b1) + sl)
                            : (reinterpret_cast<const float4*>(b2) + sl);
    const float4 wv = __ldg(wsrc);
    const float4 ov = __ldg(osrc);
    const float  nn = lo ? n1 : n2;
    const float4 v1 = make_float4(fmaf(nn, wv.x, ov.x), fmaf(nn, wv.y, ov.y),
                                  fmaf(nn, wv.z, ov.z), fmaf(nn, wv.w, ov.w));

    // --- delta / mask lane values (SELs, no branches) ---
    const float mk0 = (c1 != 0 && c1 != -1)       ? 1.0f : 0.0f;
    const float mk1 = (c2 != 0 && c2 != -1)       ? 1.0f : 0.0f;
    const float mk2 = (n1 != 0.0f && n1 != -1.0f) ? 1.0f : 0.0f;
    const float mk3 = (n2 != 0.0f && n2 != -1.0f) ? 1.0f : 0.0f;

    const float bv0 = lo ? be.x : be.y;   // half 0: features 0,1
    const float bv1 = lo ? be.z : be.w;   // half 1: features 2,3
    const float mv0 = lo ? mk0 : mk1;
    const float mv1 = lo ? mk2 : mk3;

    // --- store burst (all data ready; evict-first STG.128 streams) ---
    float4* feat4  = reinterpret_cast<float4*>(out) + (size_t)gw * 64;
    float4* delta4 = reinterpret_cast<float4*>(out + OFF_DELTA) + (size_t)gw * 64;
    float4* mask4  = reinterpret_cast<float4*>(out + OFF_MASK)  + (size_t)gw * 64;

    __stcs(feat4 + lane,       v0);
    __stcs(feat4 + lane + 32,  v1);
    __stcs(delta4 + lane,      make_float4(bv0, bv0, bv0, bv0));
    __stcs(delta4 + lane + 32, make_float4(bv1, bv1, bv1, bv1));
    __stcs(mask4 + lane,       make_float4(mv0, mv0, mv0, mv0));
    __stcs(mask4 + lane + 32,  make_float4(mv1, mv1, mv1, mv1));

    if (lane == 0) {
        __stcs(out + OFF_TIMES + gw, tm);
    }
}

// ---------------------------------------------------------------------------
// Launch
// Inputs (metadata order): cat1, cat2, num1, num2, event_time, E1, E2,
//                          w1, b1, w2, b2
// ---------------------------------------------------------------------------
extern "C" void kernel_launch(void* const* d_in, const int* in_sizes, int n_in,
                              void* d_out, int out_size)
{
    const int*   cat1  = (const int*)  d_in[0];
    const int*   cat2  = (const int*)  d_in[1];
    const float* num1  = (const float*)d_in[2];
    const float* num2  = (const float*)d_in[3];
    const float* times = (const float*)d_in[4];
    const float* E1    = (const float*)d_in[5];
    const float* E2    = (const float*)d_in[6];
    const float* w1    = (const float*)d_in[7];
    const float* b1    = (const float*)d_in[8];
    const float* w2    = (const float*)d_in[9];
    const float* b2    = (const float*)d_in[10];
    float* out = (float*)d_out;

    // Kernel 1: one 256-thread block per (f,b) row, vectorized scan
    beta_scan_kernel<<<NROWS, 256>>>(cat1, cat2, num1, num2, times);

    // Kernel 2: one warp per (b,t): 131072 warps, 8 warps/block (exact grid)
    emit_kernel<<<BT / 8, 256>>>(cat1, cat2, num1, num2, times,
                                 E1, E2, w1, b1, w2, b2, out);
}

// round 12
// speedup vs baseline: 1.0176x; 1.0176x over previous
#include <cuda_runtime.h>
#include <stdint.h>

// Problem constants (fixed by the reference: B=64, T=2048, D=64, V=100000)
#define BB 64
#define TT 2048
#define DD 64
#define BT (BB * TT)            // 131072

// Output layout (floats), tuple flattened in order:
//   features [B,T,256] @ 0
//   times    [B,T]     @ BT*256
//   delta    [B,T,256] @ BT*256 + BT
//   mask     [B,T,256] @ BT*256 + BT + BT*256
#define OFF_TIMES  (BT * 256)                 // 33554432
#define OFF_DELTA  (OFF_TIMES + BT)           // 33685504
#define OFF_MASK   (OFF_DELTA + BT * 256)     // 67239936

// Beta scratch, TRANSPOSED: g_beta[gw*4 + f] so emit reads one float4/warp.
__device__ float g_beta[4 * BT];

// ---------------------------------------------------------------------------
// Kernel 1: beta linear-recurrence scan, ALL 4 FEATURES per block.
// x_t = a_t*x_{t-1} + c_t, a_t = m_{t-1}*p_t, c_t = dt_t*p_t, x_0 = 0.
// One 512-thread block per batch b; each thread owns 4 consecutive t and
// carries 4 (A,C) pairs (one per feature). Output stored as float4 per t
// (fully coalesced, full-sector writes).
// ---------------------------------------------------------------------------
__global__ __launch_bounds__(512) void beta_scan_kernel(
    const int*   __restrict__ cat1,
    const int*   __restrict__ cat2,
    const float* __restrict__ num1,
    const float* __restrict__ num2,
    const float* __restrict__ times)
{
    const int b    = blockIdx.x;        // 0..63
    const int tid  = threadIdx.x;       // 0..511
    const int lane = tid & 31;
    const int wid  = tid >> 5;          // 0..15

    __shared__ float sA[16][4], sC[16][4];

    const float* tr  = times + b * TT;
    const int*   c1r = cat1  + b * TT;
    const int*   c2r = cat2  + b * TT;
    const float* n1r = num1  + b * TT;
    const float* n2r = num2  + b * TT;

    const int t0 = tid * 4;

    // ---- vectorized loads: 4 elems per stream ----
    const float4 tvv = __ldg(reinterpret_cast<const float4*>(tr + t0));
    float tv[4] = {tvv.x, tvv.y, tvv.z, tvv.w};
    float tprev = __shfl_up_sync(0xffffffffu, tv[3], 1);
    if (lane == 0) tprev = (t0 > 0) ? __ldg(tr + t0 - 1) : 0.0f;

    const int4 c1v = __ldg(reinterpret_cast<const int4*>(c1r + t0));
    int g0[4] = {c1v.x, c1v.y, c1v.z, c1v.w};
    int g0p = __shfl_up_sync(0xffffffffu, g0[3], 1);
    if (lane == 0) g0p = (t0 > 0) ? __ldg(c1r + t0 - 1) : 0;

    const int4 c2v = __ldg(reinterpret_cast<const int4*>(c2r + t0));
    int g1[4] = {c2v.x, c2v.y, c2v.z, c2v.w};
    int g1p = __shfl_up_sync(0xffffffffu, g1[3], 1);
    if (lane == 0) g1p = (t0 > 0) ? __ldg(c2r + t0 - 1) : 0;

    const float4 n1v = __ldg(reinterpret_cast<const float4*>(n1r + t0));
    float g2[4] = {n1v.x, n1v.y, n1v.z, n1v.w};
    float g2p = __shfl_up_sync(0xffffffffu, g2[3], 1);
    if (lane == 0) g2p = (t0 > 0) ? __ldg(n1r + t0 - 1) : 0.0f;

    const float4 n2v = __ldg(reinterpret_cast<const float4*>(n2r + t0));
    float g3[4] = {n2v.x, n2v.y, n2v.z, n2v.w};
    float g3p = __shfl_up_sync(0xffffffffu, g3[3], 1);
    if (lane == 0) g3p = (t0 > 0) ? __ldg(n2r + t0 - 1) : 0.0f;

    // ---- per-element coefficients a[f][k], c[f][k] ----
    float a[4][4], c[4][4];
    #pragma unroll
    for (int k = 0; k < 4; ++k) {
        const float tkm1 = (k == 0) ? tprev : tv[k - 1];
        const float p  = (tv[k] != -1.0f) ? 1.0f : 0.0f;
        const float dt = (tv[k] - tkm1) * p;

        const int   v0 = (k == 0) ? g0p : g0[k - 1];
        const int   v1 = (k == 0) ? g1p : g1[k - 1];
        const float v2 = (k == 0) ? g2p : g2[k - 1];
        const float v3 = (k == 0) ? g3p : g3[k - 1];

        a[0][k] = ((v0 != 0 && v0 != -1)         ? 1.0f : 0.0f) * p;
        a[1][k] = ((v1 != 0 && v1 != -1)         ? 1.0f : 0.0f) * p;
        a[2][k] = ((v2 != 0.0f && v2 != -1.0f)   ? 1.0f : 0.0f) * p;
        a[3][k] = ((v3 != 0.0f && v3 != -1.0f)   ? 1.0f : 0.0f) * p;
        c[0][k] = dt; c[1][k] = dt; c[2][k] = dt; c[3][k] = dt;
    }
    if (t0 == 0) {
        #pragma unroll
        for (int f = 0; f < 4; ++f) { a[f][0] = 0.0f; c[f][0] = 0.0f; }
    }

    // ---- sequential composition of this thread's 4 elements, per feature ----
    float A[4], C[4];
    #pragma unroll
    for (int f = 0; f < 4; ++f) {
        A[f] = a[f][0]; C[f] = c[f][0];
        #pragma unroll
        for (int k = 1; k < 4; ++k) {
            C[f] = c[f][k] + a[f][k] * C[f];
            A[f] = a[f][k] * A[f];
        }
    }

    // ---- warp inclusive scan of thread-compositions (4 features) ----
    #pragma unroll
    for (int off = 1; off < 32; off <<= 1) {
        #pragma unroll
        for (int f = 0; f < 4; ++f) {
            const float Ap = __shfl_up_sync(0xffffffffu, A[f], off);
            const float Cp = __shfl_up_sync(0xffffffffu, C[f], off);
            if (lane >= off) { C[f] = C[f] + A[f] * Cp; A[f] = A[f] * Ap; }
        }
    }
    if (lane == 31) {
        #pragma unroll
        for (int f = 0; f < 4; ++f) { sA[wid][f] = A[f]; sC[wid][f] = C[f]; }
    }
    __syncthreads();

    // ---- serial exclusive scan over 16 warp aggregates (4 threads, 1/feat) --
    if (tid < 4) {
        const int f = tid;
        float Ae = 1.0f, Ce = 0.0f;
        #pragma unroll
        for (int i = 0; i < 16; ++i) {
            const float Ai = sA[i][f], Ci = sC[i][f];
            sA[i][f] = Ae; sC[i][f] = Ce;
            Ce = Ci + Ai * Ce;
            Ae = Ai * Ae;
        }
    }
    __syncthreads();

    // ---- thread-exclusive prefix (x starts at 0 -> only C terms survive) ----
    float x[4];
    #pragma unroll
    for (int f = 0; f < 4; ++f) {
        float Ax = __shfl_up_sync(0xffffffffu, A[f], 1);
        float Cx = __shfl_up_sync(0xffffffffu, C[f], 1);
        if (lane == 0) { Ax = 1.0f; Cx = 0.0f; }
        x[f] = Cx + Ax * sC[wid][f];
    }

    // ---- apply elementwise, store float4 per t (coalesced, full sectors) ----
    float4* out4 = reinterpret_cast<float4*>(g_beta) + ((size_t)b * TT + t0);
    #pragma unroll
    for (int k = 0; k < 4; ++k) {
        #pragma unroll
        for (int f = 0; f < 4; ++f) x[f] = c[f][k] + a[f][k] * x[f];
        out4[k] = make_float4(x[0], x[1], x[2], x[3]);
    }
}

// ---------------------------------------------------------------------------
// Kernel 2: emit all outputs (R11 emit — best measured, 68.0us). One warp per
// (b,t), branchless lane-selects, loads batched ahead of the store burst,
// __stcs on all output stores, beta read as ONE float4 per warp.
// ---------------------------------------------------------------------------
__global__ void emit_kernel(const int*   __restrict__ cat1,
                            const int*   __restrict__ cat2,
                            const float* __restrict__ num1,
                            const float* __restrict__ num2,
                            const float* __restrict__ times,
                            const float* __restrict__ E1,
                            const float* __restrict__ E2,
                            const float* __restrict__ w1,
                            const float* __restrict__ b1,
                            const float* __restrict__ w2,
                            const float* __restrict__ b2,
                            float* __restrict__ out)
{
    const int gw   = blockIdx.x * (blockDim.x >> 5) + (threadIdx.x >> 5); // (b,t)
    const int lane = threadIdx.x & 31;

    const bool lo = (lane < 16);
    const int  sl = lo ? lane : (lane - 16);   // sub-lane within 16

    // --- batch all scalar loads (independent, high MLP) ---
    const int   c1 = __ldg(cat1 + gw);
    const int   c2 = __ldg(cat2 + gw);
    const float n1 = __ldg(num1 + gw);
    const float n2 = __ldg(num2 + gw);
    const float tm = __ldg(times + gw);

    // one coalesced float4: (be0, be1, be2, be3) for this (b,t)
    const float4 be = *reinterpret_cast<const float4*>(g_beta + (size_t)gw * 4);

    // --- half 0 gather: lanes 0-15 -> E1 row, lanes 16-31 -> E2 row ---
    const float4* e1row = reinterpret_cast<const float4*>(E1 + (size_t)c1 * DD);
    const float4* e2row = reinterpret_cast<const float4*>(E2 + (size_t)c2 * DD);
    const float4* src0  = lo ? (e1row + sl) : (e2row + sl);
    const float4  v0    = __ldg(src0);

    // --- half 1: lanes 0-15 -> n1*w1+b1, lanes 16-31 -> n2*w2+b2 ---
    const float4* wsrc = lo ? (reinterpret_cast<const float4*>(w1) + sl)
                            : (reinterpret_cast<const float4*>(w2) + sl);
    const float4* osrc = lo ? (reinterpret_cast<const float4*>(b1) + sl)
                            : (reinterpret_cast<const float4*>(b2) + sl);
    const float4 wv = __ldg(wsrc);
    const float4 ov = __ldg(osrc);
    const float  nn = lo ? n1 : n2;
    const float4 v1 = make_float4(fmaf(nn, wv.x, ov.x), fmaf(nn, wv.y, ov.y),
                                  fmaf(nn, wv.z, ov.z), fmaf(nn, wv.w, ov.w));

    // --- delta / mask lane values (SELs, no branches) ---
    const float mk0 = (c1 != 0 && c1 != -1)       ? 1.0f : 0.0f;
    const float mk1 = (c2 != 0 && c2 != -1)       ? 1.0f : 0.0f;
    const float mk2 = (n1 != 0.0f && n1 != -1.0f) ? 1.0f : 0.0f;
    const float mk3 = (n2 != 0.0f && n2 != -1.0f) ? 1.0f : 0.0f;

    const float bv0 = lo ? be.x : be.y;   // half 0: features 0,1
    const float bv1 = lo ? be.z : be.w;   // half 1: features 2,3
    const float mv0 = lo ? mk0 : mk1;
    const float mv1 = lo ? mk2 : mk3;

    // --- store burst (all data ready; evict-first STG.128 streams) ---
    float4* feat4  = reinterpret_cast<float4*>(out) + (size_t)gw * 64;
    float4* delta4 = reinterpret_cast<float4*>(out + OFF_DELTA) + (size_t)gw * 64;
    float4* mask4  = reinterpret_cast<float4*>(out + OFF_MASK)  + (size_t)gw * 64;

    __stcs(feat4 + lane,       v0);
    __stcs(feat4 + lane + 32,  v1);
    __stcs(delta4 + lane,      make_float4(bv0, bv0, bv0, bv0));
    __stcs(delta4 + lane + 32, make_float4(bv1, bv1, bv1, bv1));
    __stcs(mask4 + lane,       make_float4(mv0, mv0, mv0, mv0));
    __stcs(mask4 + lane + 32,  make_float4(mv1, mv1, mv1, mv1));

    if (lane == 0) {
        __stcs(out + OFF_TIMES + gw, tm);
    }
}

// ---------------------------------------------------------------------------
// Launch
// Inputs (metadata order): cat1, cat2, num1, num2, event_time, E1, E2,
//                          w1, b1, w2, b2
// ---------------------------------------------------------------------------
extern "C" void kernel_launch(void* const* d_in, const int* in_sizes, int n_in,
                              void* d_out, int out_size)
{
    const int*   cat1  = (const int*)  d_in[0];
    const int*   cat2  = (const int*)  d_in[1];
    const float* num1  = (const float*)d_in[2];
    const float* num2  = (const float*)d_in[3];
    const float* times = (const float*)d_in[4];
    const float* E1    = (const float*)d_in[5];
    const float* E2    = (const float*)d_in[6];
    const float* w1    = (const float*)d_in[7];
    const float* b1    = (const float*)d_in[8];
    const float* w2    = (const float*)d_in[9];
    const float* b2    = (const float*)d_in[10];
    float* out = (float*)d_out;

    // Kernel 1: one 512-thread block per batch, all 4 features together
    beta_scan_kernel<<<BB, 512>>>(cat1, cat2, num1, num2, times);

    // Kernel 2: one warp per (b,t): 131072 warps, 8 warps/block (exact grid)
    emit_kernel<<<BT / 8, 256>>>(cat1, cat2, num1, num2, times,
                                 E1, E2, w1, b1, w2, b2, out);
}

// round 13
// speedup vs baseline: 1.0224x; 1.0047x over previous
#include <cuda_runtime.h>
#include <stdint.h>

// Problem constants (fixed by the reference: B=64, T=2048, D=64, V=100000)
#define BB 64
#define TT 2048
#define DD 64
#define BT (BB * TT)            // 131072

// Output layout (floats), tuple flattened in order:
//   features [B,T,256] @ 0
//   times    [B,T]     @ BT*256
//   delta    [B,T,256] @ BT*256 + BT
//   mask     [B,T,256] @ BT*256 + BT + BT*256
#define OFF_TIMES  (BT * 256)                 // 33554432
#define OFF_DELTA  (OFF_TIMES + BT)           // 33685504
#define OFF_MASK   (OFF_DELTA + BT * 256)     // 67239936

// Beta scratch, TRANSPOSED: g_beta[gw*4 + f] so emit reads one float4/warp.
__device__ float g_beta[4 * BT];

// ---------------------------------------------------------------------------
// Kernel 1: beta linear-recurrence scan, ALL 4 FEATURES per block.
// One 512-thread block per batch b; each thread owns 4 consecutive t and
// carries 4 (A,C) pairs. Output stored as float4 per t (coalesced).
// ---------------------------------------------------------------------------
__global__ __launch_bounds__(512) void beta_scan_kernel(
    const int*   __restrict__ cat1,
    const int*   __restrict__ cat2,
    const float* __restrict__ num1,
    const float* __restrict__ num2,
    const float* __restrict__ times)
{
    const int b    = blockIdx.x;        // 0..63
    const int tid  = threadIdx.x;       // 0..511
    const int lane = tid & 31;
    const int wid  = tid >> 5;          // 0..15

    __shared__ float sA[16][4], sC[16][4];

    const float* tr  = times + b * TT;
    const int*   c1r = cat1  + b * TT;
    const int*   c2r = cat2  + b * TT;
    const float* n1r = num1  + b * TT;
    const float* n2r = num2  + b * TT;

    const int t0 = tid * 4;

    // ---- vectorized loads: 4 elems per stream ----
    const float4 tvv = __ldg(reinterpret_cast<const float4*>(tr + t0));
    float tv[4] = {tvv.x, tvv.y, tvv.z, tvv.w};
    float tprev = __shfl_up_sync(0xffffffffu, tv[3], 1);
    if (lane == 0) tprev = (t0 > 0) ? __ldg(tr + t0 - 1) : 0.0f;

    const int4 c1v = __ldg(reinterpret_cast<const int4*>(c1r + t0));
    int g0[4] = {c1v.x, c1v.y, c1v.z, c1v.w};
    int g0p = __shfl_up_sync(0xffffffffu, g0[3], 1);
    if (lane == 0) g0p = (t0 > 0) ? __ldg(c1r + t0 - 1) : 0;

    const int4 c2v = __ldg(reinterpret_cast<const int4*>(c2r + t0));
    int g1[4] = {c2v.x, c2v.y, c2v.z, c2v.w};
    int g1p = __shfl_up_sync(0xffffffffu, g1[3], 1);
    if (lane == 0) g1p = (t0 > 0) ? __ldg(c2r + t0 - 1) : 0;

    const float4 n1v = __ldg(reinterpret_cast<const float4*>(n1r + t0));
    float g2[4] = {n1v.x, n1v.y, n1v.z, n1v.w};
    float g2p = __shfl_up_sync(0xffffffffu, g2[3], 1);
    if (lane == 0) g2p = (t0 > 0) ? __ldg(n1r + t0 - 1) : 0.0f;

    const float4 n2v = __ldg(reinterpret_cast<const float4*>(n2r + t0));
    float g3[4] = {n2v.x, n2v.y, n2v.z, n2v.w};
    float g3p = __shfl_up_sync(0xffffffffu, g3[3], 1);
    if (lane == 0) g3p = (t0 > 0) ? __ldg(n2r + t0 - 1) : 0.0f;

    // ---- per-element coefficients a[f][k], c[f][k] ----
    float a[4][4], c[4][4];
    #pragma unroll
    for (int k = 0; k < 4; ++k) {
        const float tkm1 = (k == 0) ? tprev : tv[k - 1];
        const float p  = (tv[k] != -1.0f) ? 1.0f : 0.0f;
        const float dt = (tv[k] - tkm1) * p;

        const int   v0 = (k == 0) ? g0p : g0[k - 1];
        const int   v1 = (k == 0) ? g1p : g1[k - 1];
        const float v2 = (k == 0) ? g2p : g2[k - 1];
        const float v3 = (k == 0) ? g3p : g3[k - 1];

        a[0][k] = ((v0 != 0 && v0 != -1)         ? 1.0f : 0.0f) * p;
        a[1][k] = ((v1 != 0 && v1 != -1)         ? 1.0f : 0.0f) * p;
        a[2][k] = ((v2 != 0.0f && v2 != -1.0f)   ? 1.0f : 0.0f) * p;
        a[3][k] = ((v3 != 0.0f && v3 != -1.0f)   ? 1.0f : 0.0f) * p;
        c[0][k] = dt; c[1][k] = dt; c[2][k] = dt; c[3][k] = dt;
    }
    if (t0 == 0) {
        #pragma unroll
        for (int f = 0; f < 4; ++f) { a[f][0] = 0.0f; c[f][0] = 0.0f; }
    }

    // ---- sequential composition of this thread's 4 elements, per feature ----
    float A[4], C[4];
    #pragma unroll
    for (int f = 0; f < 4; ++f) {
        A[f] = a[f][0]; C[f] = c[f][0];
        #pragma unroll
        for (int k = 1; k < 4; ++k) {
            C[f] = c[f][k] + a[f][k] * C[f];
            A[f] = a[f][k] * A[f];
        }
    }

    // ---- warp inclusive scan (4 features) ----
    #pragma unroll
    for (int off = 1; off < 32; off <<= 1) {
        #pragma unroll
        for (int f = 0; f < 4; ++f) {
            const float Ap = __shfl_up_sync(0xffffffffu, A[f], off);
            const float Cp = __shfl_up_sync(0xffffffffu, C[f], off);
            if (lane >= off) { C[f] = C[f] + A[f] * Cp; A[f] = A[f] * Ap; }
        }
    }
    if (lane == 31) {
        #pragma unroll
        for (int f = 0; f < 4; ++f) { sA[wid][f] = A[f]; sC[wid][f] = C[f]; }
    }
    __syncthreads();

    // ---- serial exclusive scan over 16 warp aggregates (4 threads) ----
    if (tid < 4) {
        const int f = tid;
        float Ae = 1.0f, Ce = 0.0f;
        #pragma unroll
        for (int i = 0; i < 16; ++i) {
            const float Ai = sA[i][f], Ci = sC[i][f];
            sA[i][f] = Ae; sC[i][f] = Ce;
            Ce = Ci + Ai * Ce;
            Ae = Ai * Ae;
        }
    }
    __syncthreads();

    // ---- thread-exclusive prefix ----
    float x[4];
    #pragma unroll
    for (int f = 0; f < 4; ++f) {
        float Ax = __shfl_up_sync(0xffffffffu, A[f], 1);
        float Cx = __shfl_up_sync(0xffffffffu, C[f], 1);
        if (lane == 0) { Ax = 1.0f; Cx = 0.0f; }
        x[f] = Cx + Ax * sC[wid][f];
    }

    // ---- apply elementwise, store float4 per t (coalesced) ----
    float4* out4 = reinterpret_cast<float4*>(g_beta) + ((size_t)b * TT + t0);
    #pragma unroll
    for (int k = 0; k < 4; ++k) {
        #pragma unroll
        for (int f = 0; f < 4; ++f) x[f] = c[f][k] + a[f][k] * x[f];
        out4[k] = make_float4(x[0], x[1], x[2], x[3]);
    }
}

// ---------------------------------------------------------------------------
// Kernel 2: emit. PDL consumer — launched with programmatic stream
// serialization so it overlaps beta's execution. All beta-independent work
// (loads, features/mask/times stores) happens BEFORE
// cudaGridDependencySynchronize(); the beta-dependent delta stores after.
// ---------------------------------------------------------------------------
__global__ void emit_kernel(const int*   __restrict__ cat1,
                            const int*   __restrict__ cat2,
                            const float* __restrict__ num1,
                            const float* __restrict__ num2,
                            const float* __restrict__ times,
                            const float* __restrict__ E1,
                            const float* __restrict__ E2,
                            const float* __restrict__ w1,
                            const float* __restrict__ b1,
                            const float* __restrict__ w2,
                            const float* __restrict__ b2,
                            float* __restrict__ out)
{
    const int gw   = blockIdx.x * (blockDim.x >> 5) + (threadIdx.x >> 5); // (b,t)
    const int lane = threadIdx.x & 31;

    const bool lo = (lane < 16);
    const int  sl = lo ? lane : (lane - 16);   // sub-lane within 16

    // --- beta-independent scalar loads ---
    const int   c1 = __ldg(cat1 + gw);
    const int   c2 = __ldg(cat2 + gw);
    const float n1 = __ldg(num1 + gw);
    const float n2 = __ldg(num2 + gw);
    const float tm = __ldg(times + gw);

    // --- half 0 gather: lanes 0-15 -> E1 row, lanes 16-31 -> E2 row ---
    const float4* e1row = reinterpret_cast<const float4*>(E1 + (size_t)c1 * DD);
    const float4* e2row = reinterpret_cast<const float4*>(E2 + (size_t)c2 * DD);
    const float4* src0  = lo ? (e1row + sl) : (e2row + sl);
    const float4  v0    = __ldg(src0);

    // --- half 1: lanes 0-15 -> n1*w1+b1, lanes 16-31 -> n2*w2+b2 ---
    const float4* wsrc = lo ? (reinterpret_cast<const float4*>(w1) + sl)
                            : (reinterpret_cast<const float4*>(w2) + sl);
    const float4* osrc = lo ? (reinterpret_cast<const float4*>(b1) + sl)
                            : (reinterpret_cast<const float4*>(b2) + sl);
    const float4 wv = __ldg(wsrc);
    const float4 ov = __ldg(osrc);
    const float  nn = lo ? n1 : n2;
    const float4 v1 = make_float4(fmaf(nn, wv.x, ov.x), fmaf(nn, wv.y, ov.y),
                                  fmaf(nn, wv.z, ov.z), fmaf(nn, wv.w, ov.w));

    // --- mask lane values ---
    const float mk0 = (c1 != 0 && c1 != -1)       ? 1.0f : 0.0f;
    const float mk1 = (c2 != 0 && c2 != -1)       ? 1.0f : 0.0f;
    const float mk2 = (n1 != 0.0f && n1 != -1.0f) ? 1.0f : 0.0f;
    const float mk3 = (n2 != 0.0f && n2 != -1.0f) ? 1.0f : 0.0f;
    const float mv0 = lo ? mk0 : mk1;
    const float mv1 = lo ? mk2 : mk3;

    float4* feat4  = reinterpret_cast<float4*>(out) + (size_t)gw * 64;
    float4* delta4 = reinterpret_cast<float4*>(out + OFF_DELTA) + (size_t)gw * 64;
    float4* mask4  = reinterpret_cast<float4*>(out + OFF_MASK)  + (size_t)gw * 64;

    // --- beta-independent stores (keep DRAM busy during the PDL wait) ---
    __stcs(feat4 + lane,      v0);
    __stcs(feat4 + lane + 32, v1);
    __stcs(mask4 + lane,      make_float4(mv0, mv0, mv0, mv0));
    __stcs(mask4 + lane + 32, make_float4(mv1, mv1, mv1, mv1));
    if (lane == 0) {
        __stcs(out + OFF_TIMES + gw, tm);
    }

    // --- wait for beta grid (HW-backed PDL dependency) ---
    cudaGridDependencySynchronize();

    // --- beta-dependent delta stores ---
    const float4 be = *reinterpret_cast<const float4*>(g_beta + (size_t)gw * 4);
    const float bv0 = lo ? be.x : be.y;   // half 0: features 0,1
    const float bv1 = lo ? be.z : be.w;   // half 1: features 2,3

    __stcs(delta4 + lane,      make_float4(bv0, bv0, bv0, bv0));
    __stcs(delta4 + lane + 32, make_float4(bv1, bv1, bv1, bv1));
}

// ---------------------------------------------------------------------------
// Launch
// Inputs (metadata order): cat1, cat2, num1, num2, event_time, E1, E2,
//                          w1, b1, w2, b2
// ---------------------------------------------------------------------------
extern "C" void kernel_launch(void* const* d_in, const int* in_sizes, int n_in,
                              void* d_out, int out_size)
{
    const int*   cat1  = (const int*)  d_in[0];
    const int*   cat2  = (const int*)  d_in[1];
    const float* num1  = (const float*)d_in[2];
    const float* num2  = (const float*)d_in[3];
    const float* times = (const float*)d_in[4];
    const float* E1    = (const float*)d_in[5];
    const float* E2    = (const float*)d_in[6];
    const float* w1    = (const float*)d_in[7];
    const float* b1    = (const float*)d_in[8];
    const float* w2    = (const float*)d_in[9];
    const float* b2    = (const float*)d_in[10];
    float* out = (float*)d_out;

    // Kernel 1: one 512-thread block per batch, all 4 features together
    beta_scan_kernel<<<BB, 512>>>(cat1, cat2, num1, num2, times);

    // Kernel 2: emit, launched with Programmatic Dependent Launch so its
    // prologue overlaps beta's execution.
    cudaLaunchConfig_t cfg = {};
    cfg.gridDim  = dim3(BT / 8, 1, 1);
    cfg.blockDim = dim3(256, 1, 1);
    cfg.dynamicSmemBytes = 0;
    cfg.stream = 0;  // legacy default stream (the capture stream)

    cudaLaunchAttribute attrs[1];
    attrs[0].id = cudaLaunchAttributeProgrammaticStreamSerialization;
    attrs[0].val.programmaticStreamSerializationAllowed = 1;
    cfg.attrs = attrs;
    cfg.numAttrs = 1;

    cudaLaunchKernelEx(&cfg, emit_kernel,
                       cat1, cat2, num1, num2, times,
                       E1, E2, w1, b1, w2, b2, out);
}

// round 14
// speedup vs baseline: 1.0490x; 1.0261x over previous
#include <cuda_runtime.h>
#include <stdint.h>

// Problem constants (fixed by the reference: B=64, T=2048, D=64, V=100000)
#define BB 64
#define TT 2048
#define DD 64
#define BT (BB * TT)            // 131072

// Output layout (floats), tuple flattened in order:
//   features [B,T,256] @ 0
//   times    [B,T]     @ BT*256
//   delta    [B,T,256] @ BT*256 + BT
//   mask     [B,T,256] @ BT*256 + BT + BT*256
#define OFF_TIMES  (BT * 256)                 // 33554432
#define OFF_DELTA  (OFF_TIMES + BT)           // 33685504
#define OFF_MASK   (OFF_DELTA + BT * 256)     // 67239936

// Beta scratch, TRANSPOSED: g_beta[gw*4 + f] so emit reads one float4/warp.
__device__ float g_beta[4 * BT];

// ---------------------------------------------------------------------------
// Kernel 1: beta linear-recurrence scan, ALL 4 FEATURES per block.
// One 512-thread block per batch b; each thread owns 4 consecutive t and
// carries 4 (A,C) pairs. Output stored as float4 per t (coalesced).
// PDL primary: triggers programmatic launch completion at ENTRY so the emit
// grid starts concurrently; g_beta visibility is enforced by the consumer's
// cudaGridDependencySynchronize (waits for full completion of this grid).
// ---------------------------------------------------------------------------
__global__ __launch_bounds__(512) void beta_scan_kernel(
    const int*   __restrict__ cat1,
    const int*   __restrict__ cat2,
    const float* __restrict__ num1,
    const float* __restrict__ num2,
    const float* __restrict__ times)
{
    // Fire the PDL trigger immediately: allow the dependent emit grid to begin.
    cudaTriggerProgrammaticLaunchCompletion();

    const int b    = blockIdx.x;        // 0..63
    const int tid  = threadIdx.x;       // 0..511
    const int lane = tid & 31;
    const int wid  = tid >> 5;          // 0..15

    __shared__ float sA[16][4], sC[16][4];

    const float* tr  = times + b * TT;
    const int*   c1r = cat1  + b * TT;
    const int*   c2r = cat2  + b * TT;
    const float* n1r = num1  + b * TT;
    const float* n2r = num2  + b * TT;

    const int t0 = tid * 4;

    // ---- vectorized loads: 4 elems per stream ----
    const float4 tvv = __ldg(reinterpret_cast<const float4*>(tr + t0));
    float tv[4] = {tvv.x, tvv.y, tvv.z, tvv.w};
    float tprev = __shfl_up_sync(0xffffffffu, tv[3], 1);
    if (lane == 0) tprev = (t0 > 0) ? __ldg(tr + t0 - 1) : 0.0f;

    const int4 c1v = __ldg(reinterpret_cast<const int4*>(c1r + t0));
    int g0[4] = {c1v.x, c1v.y, c1v.z, c1v.w};
    int g0p = __shfl_up_sync(0xffffffffu, g0[3], 1);
    if (lane == 0) g0p = (t0 > 0) ? __ldg(c1r + t0 - 1) : 0;

    const int4 c2v = __ldg(reinterpret_cast<const int4*>(c2r + t0));
    int g1[4] = {c2v.x, c2v.y, c2v.z, c2v.w};
    int g1p = __shfl_up_sync(0xffffffffu, g1[3], 1);
    if (lane == 0) g1p = (t0 > 0) ? __ldg(c2r + t0 - 1) : 0;

    const float4 n1v = __ldg(reinterpret_cast<const float4*>(n1r + t0));
    float g2[4] = {n1v.x, n1v.y, n1v.z, n1v.w};
    float g2p = __shfl_up_sync(0xffffffffu, g2[3], 1);
    if (lane == 0) g2p = (t0 > 0) ? __ldg(n1r + t0 - 1) : 0.0f;

    const float4 n2v = __ldg(reinterpret_cast<const float4*>(n2r + t0));
    float g3[4] = {n2v.x, n2v.y, n2v.z, n2v.w};
    float g3p = __shfl_up_sync(0xffffffffu, g3[3], 1);
    if (lane == 0) g3p = (t0 > 0) ? __ldg(n2r + t0 - 1) : 0.0f;

    // ---- per-element coefficients a[f][k], c[f][k] ----
    float a[4][4], c[4][4];
    #pragma unroll
    for (int k = 0; k < 4; ++k) {
        const float tkm1 = (k == 0) ? tprev : tv[k - 1];
        const float p  = (tv[k] != -1.0f) ? 1.0f : 0.0f;
        const float dt = (tv[k] - tkm1) * p;

        const int   v0 = (k == 0) ? g0p : g0[k - 1];
        const int   v1 = (k == 0) ? g1p : g1[k - 1];
        const float v2 = (k == 0) ? g2p : g2[k - 1];
        const float v3 = (k == 0) ? g3p : g3[k - 1];

        a[0][k] = ((v0 != 0 && v0 != -1)         ? 1.0f : 0.0f) * p;
        a[1][k] = ((v1 != 0 && v1 != -1)         ? 1.0f : 0.0f) * p;
        a[2][k] = ((v2 != 0.0f && v2 != -1.0f)   ? 1.0f : 0.0f) * p;
        a[3][k] = ((v3 != 0.0f && v3 != -1.0f)   ? 1.0f : 0.0f) * p;
        c[0][k] = dt; c[1][k] = dt; c[2][k] = dt; c[3][k] = dt;
    }
    if (t0 == 0) {
        #pragma unroll
        for (int f = 0; f < 4; ++f) { a[f][0] = 0.0f; c[f][0] = 0.0f; }
    }

    // ---- sequential composition of this thread's 4 elements, per feature ----
    float A[4], C[4];
    #pragma unroll
    for (int f = 0; f < 4; ++f) {
        A[f] = a[f][0]; C[f] = c[f][0];
        #pragma unroll
        for (int k = 1; k < 4; ++k) {
            C[f] = c[f][k] + a[f][k] * C[f];
            A[f] = a[f][k] * A[f];
        }
    }

    // ---- warp inclusive scan (4 features) ----
    #pragma unroll
    for (int off = 1; off < 32; off <<= 1) {
        #pragma unroll
        for (int f = 0; f < 4; ++f) {
            const float Ap = __shfl_up_sync(0xffffffffu, A[f], off);
            const float Cp = __shfl_up_sync(0xffffffffu, C[f], off);
            if (lane >= off) { C[f] = C[f] + A[f] * Cp; A[f] = A[f] * Ap; }
        }
    }
    if (lane == 31) {
        #pragma unroll
        for (int f = 0; f < 4; ++f) { sA[wid][f] = A[f]; sC[wid][f] = C[f]; }
    }
    __syncthreads();

    // ---- serial exclusive scan over 16 warp aggregates (4 threads) ----
    if (tid < 4) {
        const int f = tid;
        float Ae = 1.0f, Ce = 0.0f;
        #pragma unroll
        for (int i = 0; i < 16; ++i) {
            const float Ai = sA[i][f], Ci = sC[i][f];
            sA[i][f] = Ae; sC[i][f] = Ce;
            Ce = Ci + Ai * Ce;
            Ae = Ai * Ae;
        }
    }
    __syncthreads();

    // ---- thread-exclusive prefix ----
    float x[4];
    #pragma unroll
    for (int f = 0; f < 4; ++f) {
        float Ax = __shfl_up_sync(0xffffffffu, A[f], 1);
        float Cx = __shfl_up_sync(0xffffffffu, C[f], 1);
        if (lane == 0) { Ax = 1.0f; Cx = 0.0f; }
        x[f] = Cx + Ax * sC[wid][f];
    }

    // ---- apply elementwise, store float4 per t (coalesced) ----
    float4* out4 = reinterpret_cast<float4*>(g_beta) + ((size_t)b * TT + t0);
    #pragma unroll
    for (int k = 0; k < 4; ++k) {
        #pragma unroll
        for (int f = 0; f < 4; ++f) x[f] = c[f][k] + a[f][k] * x[f];
        out4[k] = make_float4(x[0], x[1], x[2], x[3]);
    }
}

// ---------------------------------------------------------------------------
// Kernel 2: emit. PDL consumer. Beta-independent work (loads, features/mask/
// times stores) BEFORE cudaGridDependencySynchronize(); delta stores after.
// ---------------------------------------------------------------------------
__global__ void emit_kernel(const int*   __restrict__ cat1,
                            const int*   __restrict__ cat2,
                            const float* __restrict__ num1,
                            const float* __restrict__ num2,
                            const float* __restrict__ times,
                            const float* __restrict__ E1,
                            const float* __restrict__ E2,
                            const float* __restrict__ w1,
                            const float* __restrict__ b1,
                            const float* __restrict__ w2,
                            const float* __restrict__ b2,
                            float* __restrict__ out)
{
    const int gw   = blockIdx.x * (blockDim.x >> 5) + (threadIdx.x >> 5); // (b,t)
    const int lane = threadIdx.x & 31;

    const bool lo = (lane < 16);
    const int  sl = lo ? lane : (lane - 16);   // sub-lane within 16

    // --- beta-independent scalar loads ---
    const int   c1 = __ldg(cat1 + gw);
    const int   c2 = __ldg(cat2 + gw);
    const float n1 = __ldg(num1 + gw);
    const float n2 = __ldg(num2 + gw);
    const float tm = __ldg(times + gw);

    // --- half 0 gather: lanes 0-15 -> E1 row, lanes 16-31 -> E2 row ---
    const float4* e1row = reinterpret_cast<const float4*>(E1 + (size_t)c1 * DD);
    const float4* e2row = reinterpret_cast<const float4*>(E2 + (size_t)c2 * DD);
    const float4* src0  = lo ? (e1row + sl) : (e2row + sl);
    const float4  v0    = __ldg(src0);

    // --- half 1: lanes 0-15 -> n1*w1+b1, lanes 16-31 -> n2*w2+b2 ---
    const float4* wsrc = lo ? (reinterpret_cast<const float4*>(w1) + sl)
                            : (reinterpret_cast<const float4*>(w2) + sl);
    const float4* osrc = lo ? (reinterpret_cast<const float4*>(b1) + sl)
                            : (reinterpret_cast<const float4*>(b2) + sl);
    const float4 wv = __ldg(wsrc);
    const float4 ov = __ldg(osrc);
    const float  nn = lo ? n1 : n2;
    const float4 v1 = make_float4(fmaf(nn, wv.x, ov.x), fmaf(nn, wv.y, ov.y),
                                  fmaf(nn, wv.z, ov.z), fmaf(nn, wv.w, ov.w));

    // --- mask lane values ---
    const float mk0 = (c1 != 0 && c1 != -1)       ? 1.0f : 0.0f;
    const float mk1 = (c2 != 0 && c2 != -1)       ? 1.0f : 0.0f;
    const float mk2 = (n1 != 0.0f && n1 != -1.0f) ? 1.0f : 0.0f;
    const float mk3 = (n2 != 0.0f && n2 != -1.0f) ? 1.0f : 0.0f;
    const float mv0 = lo ? mk0 : mk1;
    const float mv1 = lo ? mk2 : mk3;

    float4* feat4  = reinterpret_cast<float4*>(out) + (size_t)gw * 64;
    float4* delta4 = reinterpret_cast<float4*>(out + OFF_DELTA) + (size_t)gw * 64;
    float4* mask4  = reinterpret_cast<float4*>(out + OFF_MASK)  + (size_t)gw * 64;

    // --- beta-independent stores (keep DRAM busy during the PDL wait) ---
    __stcs(feat4 + lane,      v0);
    __stcs(feat4 + lane + 32, v1);
    __stcs(mask4 + lane,      make_float4(mv0, mv0, mv0, mv0));
    __stcs(mask4 + lane + 32, make_float4(mv1, mv1, mv1, mv1));
    if (lane == 0) {
        __stcs(out + OFF_TIMES + gw, tm);
    }

    // --- wait for beta grid completion (HW-backed PDL dependency) ---
    cudaGridDependencySynchronize();

    // --- beta-dependent delta stores ---
    const float4 be = *reinterpret_cast<const float4*>(g_beta + (size_t)gw * 4);
    const float bv0 = lo ? be.x : be.y;   // half 0: features 0,1
    const float bv1 = lo ? be.z : be.w;   // half 1: features 2,3

    __stcs(delta4 + lane,      make_float4(bv0, bv0, bv0, bv0));
    __stcs(delta4 + lane + 32, make_float4(bv1, bv1, bv1, bv1));
}

// ---------------------------------------------------------------------------
// Launch
// Inputs (metadata order): cat1, cat2, num1, num2, event_time, E1, E2,
//                          w1, b1, w2, b2
// ---------------------------------------------------------------------------
extern "C" void kernel_launch(void* const* d_in, const int* in_sizes, int n_in,
                              void* d_out, int out_size)
{
    const int*   cat1  = (const int*)  d_in[0];
    const int*   cat2  = (const int*)  d_in[1];
    const float* num1  = (const float*)d_in[2];
    const float* num2  = (const float*)d_in[3];
    const float* times = (const float*)d_in[4];
    const float* E1    = (const float*)d_in[5];
    const float* E2    = (const float*)d_in[6];
    const float* w1    = (const float*)d_in[7];
    const float* b1    = (const float*)d_in[8];
    const float* w2    = (const float*)d_in[9];
    const float* b2    = (const float*)d_in[10];
    float* out = (float*)d_out;

    // Kernel 1: one 512-thread block per batch, all 4 features together
    beta_scan_kernel<<<BB, 512>>>(cat1, cat2, num1, num2, times);

    // Kernel 2: emit, PDL — overlaps with beta (which triggers at entry).
    cudaLaunchConfig_t cfg = {};
    cfg.gridDim  = dim3(BT / 8, 1, 1);
    cfg.blockDim = dim3(256, 1, 1);
    cfg.dynamicSmemBytes = 0;
    cfg.stream = 0;  // legacy default stream (the capture stream)

    cudaLaunchAttribute attrs[1];
    attrs[0].id = cudaLaunchAttributeProgrammaticStreamSerialization;
    attrs[0].val.programmaticStreamSerializationAllowed = 1;
    cfg.attrs = attrs;
    cfg.numAttrs = 1;

    cudaLaunchKernelEx(&cfg, emit_kernel,
                       cat1, cat2, num1, num2, times,
                       E1, E2, w1, b1, w2, b2, out);
}